// round 5
// baseline (speedup 1.0000x reference)
#include <cuda_runtime.h>

// Problem constants (fixed by the reference)
#define B       32
#define N       2048
#define OUTD    100
#define JSPLITS 16
#define JCHUNK  (N / JSPLITS)        // 128
#define BPG     4                    // batch rows per block
#define BGROUPS (B / BPG)            // 8
#define GRID    (JSPLITS * BGROUPS)  // 128 blocks
#define NT      512
#define NW      16
#define J_PER_WARP (JCHUNK / NW)     // 8

// Reference: out[b,o] = sum_j rem[b,j] W[j,o],
//   rem[b,j] = (q - (N*c + S_b))^2, c = (int)q, S_b = sum_j c  (exact ints < 2^24)
// Expansion with e = q - N*c (block-local):
//   out[b,o] = A - 2*S_b*B + S_b^2*C,  A = sum e^2 W, B = sum e W, C = sum_j W.
// Fixed-order sums -> deterministic.

__device__ float2       g_AB[JSPLITS][B][OUTD];          // (A, B) partials
__device__ float        g_Cv[BGROUPS][JSPLITS][OUTD];    // per-bgroup C partials
__device__ int          g_S [JSPLITS][B];
__device__ unsigned int g_count[BGROUPS];                // zero-initialized

struct Smem {
    float2 ep[2][2][JCHUNK];        // [row-pair][0:e,1:e2][col] = (row2p, row2p+1)
    float2 part[NW][BPG * OUTD];    // (A,B) per-warp partials  51.2 KB
    float  cpart[NW][OUTD];         // C per-warp partials       6.4 KB
    int    qsum[NW];
    int    is_last;
};

__device__ __forceinline__ unsigned long long pk2(float lo, float hi) {
    unsigned long long r;
    asm("mov.b64 %0, {%1, %2};" : "=l"(r) : "f"(lo), "f"(hi));
    return r;
}
__device__ __forceinline__ void fma2(unsigned long long& d,
                                     unsigned long long a, unsigned long long b) {
    asm("fma.rn.f32x2 %0, %1, %2, %3;" : "=l"(d) : "l"(a), "l"(b), "l"(d));
}
__device__ __forceinline__ float low2(unsigned long long v) {
    float lo, hi; asm("mov.b64 {%0, %1}, %2;" : "=f"(lo), "=f"(hi) : "l"(v)); return lo;
}
__device__ __forceinline__ float high2(unsigned long long v) {
    float lo, hi; asm("mov.b64 {%0, %1}, %2;" : "=f"(lo), "=f"(hi) : "l"(v)); return hi;
}

__global__ __launch_bounds__(NT, 1)
void fused_rowstat_kernel(const float* __restrict__ q,
                          const float* __restrict__ W,
                          float* __restrict__ out)
{
    extern __shared__ Smem sm[];
    const int tid  = threadIdx.x;
    const int wid  = tid >> 5;
    const int lane = tid & 31;
    const int s    = blockIdx.x & (JSPLITS - 1);
    const int bg   = blockIdx.x >> 4;
    const int j0   = s * JCHUNK;

    // ---- Prefetch W slice into registers (independent of q) ----
    const int g  = lane;                 // g<25 owns outputs 4g..4g+3
    const int jw = wid * J_PER_WARP;
    float4 w4[J_PER_WARP];
    if (g < 25) {
        const float* Wg = W + (size_t)(j0 + jw) * OUTD + g * 4;
        #pragma unroll
        for (int jj = 0; jj < J_PER_WARP; ++jj)
            w4[jj] = *reinterpret_cast<const float4*>(Wg + jj * OUTD);
    }

    // ---- Load q chunk, build (e, e^2) row-pairs in smem, int partial sums ----
    {
        const int r    = tid >> 7;       // row in group 0..3
        const int col  = tid & 127;
        const int pair = r >> 1, half = r & 1;
        float qv = q[(size_t)(bg * BPG + r) * N + j0 + col];
        int   c  = (int)qv;
        float e  = qv - (float)(N * c);
        reinterpret_cast<float*>(&sm->ep[pair][0][col])[half] = e;
        reinterpret_cast<float*>(&sm->ep[pair][1][col])[half] = e * e;

        int ss = c;
        #pragma unroll
        for (int o = 16; o > 0; o >>= 1) ss += __shfl_xor_sync(0xFFFFFFFFu, ss, o);
        if (lane == 0) sm->qsum[wid] = ss;
    }
    __syncthreads();

    if (tid < BPG)
        g_S[s][bg * BPG + tid] = sm->qsum[4*tid] + sm->qsum[4*tid+1]
                               + sm->qsum[4*tid+2] + sm->qsum[4*tid+3];

    // ---- GEMV: packed f32x2 over row-pairs ----
    if (g < 25) {
        unsigned long long accA[2][4], accB[2][4];
        float aC[4] = {0.f, 0.f, 0.f, 0.f};
        #pragma unroll
        for (int p = 0; p < 2; ++p)
            #pragma unroll
            for (int k = 0; k < 4; ++k) { accA[p][k] = 0ull; accB[p][k] = 0ull; }

        #pragma unroll
        for (int jj = 0; jj < J_PER_WARP; ++jj) {
            const int col = jw + jj;
            unsigned long long pe0 = *reinterpret_cast<const unsigned long long*>(&sm->ep[0][0][col]);
            unsigned long long pe1 = *reinterpret_cast<const unsigned long long*>(&sm->ep[1][0][col]);
            unsigned long long ps0 = *reinterpret_cast<const unsigned long long*>(&sm->ep[0][1][col]);
            unsigned long long ps1 = *reinterpret_cast<const unsigned long long*>(&sm->ep[1][1][col]);
            const float4 w = w4[jj];
            unsigned long long wd[4] = { pk2(w.x, w.x), pk2(w.y, w.y),
                                         pk2(w.z, w.z), pk2(w.w, w.w) };
            aC[0] += w.x; aC[1] += w.y; aC[2] += w.z; aC[3] += w.w;
            #pragma unroll
            for (int k = 0; k < 4; ++k) {
                fma2(accA[0][k], ps0, wd[k]);
                fma2(accA[1][k], ps1, wd[k]);
                fma2(accB[0][k], pe0, wd[k]);
                fma2(accB[1][k], pe1, wd[k]);
            }
        }

        // Store per-warp (A,B) partials and C partials
        #pragma unroll
        for (int p = 0; p < 2; ++p)
            #pragma unroll
            for (int k = 0; k < 4; ++k) {
                sm->part[wid][(2*p + 0) * OUTD + 4*g + k] =
                    make_float2(low2 (accA[p][k]), low2 (accB[p][k]));
                sm->part[wid][(2*p + 1) * OUTD + 4*g + k] =
                    make_float2(high2(accA[p][k]), high2(accB[p][k]));
            }
        *reinterpret_cast<float4*>(&sm->cpart[wid][4*g]) =
            make_float4(aC[0], aC[1], aC[2], aC[3]);
    }
    __syncthreads();

    // ---- Reduce across 16 warps, publish split partials ----
    if (tid < BPG * OUTD) {
        float A = 0.f, Bv = 0.f;
        #pragma unroll
        for (int w = 0; w < NW; ++w) {
            float2 v = sm->part[w][tid];
            A += v.x; Bv += v.y;
        }
        const int rr = tid / OUTD;
        const int o  = tid - rr * OUTD;
        g_AB[s][bg * BPG + rr][o] = make_float2(A, Bv);
    } else if (tid < BPG * OUTD + OUTD) {
        const int o = tid - BPG * OUTD;
        float C = 0.f;
        #pragma unroll
        for (int w = 0; w < NW; ++w) C += sm->cpart[w][o];
        g_Cv[bg][s][o] = C;
    }
    __threadfence();
    __syncthreads();

    // ---- Per-bgroup last block combines its 16 splits ----
    if (tid == 0) {
        unsigned old = atomicAdd(&g_count[bg], 1u);
        sm->is_last = (old == JSPLITS - 1);
        if (sm->is_last) g_count[bg] = 0;          // self-reset for graph replay
    }
    __syncthreads();

    if (sm->is_last && tid < BPG * OUTD) {
        const int rr = tid / OUTD;
        const int o  = tid - rr * OUTD;
        const int b  = bg * BPG + rr;
        float A = 0.f, Bv = 0.f, C = 0.f;
        int   S = 0;
        #pragma unroll
        for (int sp = 0; sp < JSPLITS; ++sp) {
            float2 ab = g_AB[sp][b][o];
            A += ab.x; Bv += ab.y;
            C += g_Cv[bg][sp][o];
            S += g_S[sp][b];
        }
        const float Sf = (float)S;
        out[b * OUTD + o] = fmaf(Sf * Sf, C, fmaf(-2.f * Sf, Bv, A));
    }
}

extern "C" void kernel_launch(void* const* d_in, const int* in_sizes, int n_in,
                              void* d_out, int out_size)
{
    const float* q = (const float*)d_in[0];   // [32, 2048] f32
    const float* W = (const float*)d_in[1];   // [2048, 100] f32
    float* out = (float*)d_out;               // [32, 100] f32
    (void)in_sizes; (void)n_in; (void)out_size;

    static const size_t smem_bytes = sizeof(Smem);
    cudaFuncSetAttribute(fused_rowstat_kernel,
                         cudaFuncAttributeMaxDynamicSharedMemorySize,
                         (int)smem_bytes);
    fused_rowstat_kernel<<<GRID, NT, smem_bytes>>>(q, W, out);
}